// round 16
// baseline (speedup 1.0000x reference)
#include <cuda_runtime.h>
#include <cuda_fp16.h>

typedef unsigned long long ull;

// ---------------- problem constants (shapes fixed by the dataset) -----------
#define MAXN 100000
#define MAXE 3342336
#define HC   64
#define MAXG 512
#define EPSV 1e-5f

// ---------------- device scratch (static; no allocation) --------------------
__device__ __half g_bufH[MAXN * HC];     // scaled projected features, fp16
__device__ __half g_bufF[MAXN * HC];     // hidden activations h, fp16
__device__ float  g_dis[MAXN];           // rsqrt(deg)
__device__ int    g_deg[MAXN];           // in-degree (w/o self loop)
__device__ int    g_rowptr[MAXN + 1];
__device__ int    g_cursor[MAXN];
__device__ int    g_csr[MAXE];           // src ids grouped by dst
__device__ int    g_bsum[512];
__device__ float  g_sum1[HC], g_sq1[HC], g_sum2[HC], g_sq2[HC];
__device__ float  g_pool[MAXG * HC];     // raw pooled sums (pre-BN)
__device__ float  g_cnt[MAXG];
__device__ int    g_is64;

// ---------------- host-side stream/event objects (created pre-main) ---------
static cudaStream_t hx_s2;
static cudaEvent_t  hx_fork, hx_dis, hx_join;
namespace {
struct HXInit {
    HXInit() {
        cudaStreamCreateWithFlags(&hx_s2, cudaStreamNonBlocking);
        cudaEventCreateWithFlags(&hx_fork, cudaEventDisableTiming);
        cudaEventCreateWithFlags(&hx_dis,  cudaEventDisableTiming);
        cudaEventCreateWithFlags(&hx_join, cudaEventDisableTiming);
    }
};
static HXInit hx_init;
}

// ---------------- dtype-agnostic index load ---------------------------------
__device__ __forceinline__ long long ld_idx(const void* p, long long i) {
    if (g_is64) return ((const long long*)p)[i];
    return (long long)((const int*)p)[i];
}

// ---------------- packed f32x2 helpers (Blackwell) --------------------------
__device__ __forceinline__ ull dupf(float a) {
    ull r; unsigned int u = __float_as_uint(a);
    asm("mov.b64 %0, {%1, %1};" : "=l"(r) : "r"(u));
    return r;
}
__device__ __forceinline__ void ffma2(ull& d, ull a, ull b) {
    asm("fma.rn.f32x2 %0, %1, %2, %0;" : "+l"(d) : "l"(a), "l"(b));
}
__device__ __forceinline__ float2 unpk(ull v) {
    unsigned int lo, hi;
    asm("mov.b64 {%0, %1}, %2;" : "=r"(lo), "=r"(hi) : "l"(v));
    return make_float2(__uint_as_float(lo), __uint_as_float(hi));
}

// ---------------- init: zero deg/pool/cnt/bn sums (+dtype detect, thread 0) --
__global__ void k_zero(const void* ei, long long n) {
    long long i = blockIdx.x * (long long)blockDim.x + threadIdx.x;
    if (i == 0) {
        const long long* p = (const long long*)ei;
        int ok = 1;
        for (int j = 0; j < 64; j++) {
            long long v = p[j];
            if (v < 0 || v >= n) { ok = 0; break; }
        }
        g_is64 = ok;
    }
    if (i < n)          g_deg[i] = 0;
    if (i < MAXG * HC)  g_pool[i] = 0.0f;
    if (i < MAXG)       g_cnt[i] = 0.0f;
    if (i < HC) { g_sum1[i] = 0.f; g_sq1[i] = 0.f; g_sum2[i] = 0.f; g_sq2[i] = 0.f; }
}

// ---------------- histogram of dst, 2 edges per thread -----------------------
__global__ void k_hist(const void* ei, long long E) {
    long long e = (blockIdx.x * (long long)blockDim.x + threadIdx.x) * 2;
    if (e >= E) return;
    if (g_is64) {
        const long long* p = (const long long*)ei + E + e;
        atomicAdd(&g_deg[p[0]], 1);
        if (e + 1 < E) atomicAdd(&g_deg[p[1]], 1);
    } else {
        const int* p = (const int*)ei + E + e;
        if (e + 1 < E) {
            int2 d = *(const int2*)p;
            atomicAdd(&g_deg[d.x], 1);
            atomicAdd(&g_deg[d.y], 1);
        } else {
            atomicAdd(&g_deg[p[0]], 1);
        }
    }
}

// ---------------- scan pass 1: block-local exclusive scan --------------------
__global__ void k_scan1(long long n) {
    __shared__ int wsum[8];
    int t = threadIdx.x;
    long long i = blockIdx.x * 256LL + t;
    int v = (i < n) ? g_deg[i] : 0;
    int x = v;
#pragma unroll
    for (int o = 1; o < 32; o <<= 1) {
        int y = __shfl_up_sync(~0u, x, o);
        if ((t & 31) >= o) x += y;
    }
    if ((t & 31) == 31) wsum[t >> 5] = x;
    __syncthreads();
    if (t < 8) {
        int y = wsum[t];
#pragma unroll
        for (int o = 1; o < 8; o <<= 1) {
            int z = __shfl_up_sync(0xff, y, o);
            if (t >= o) y += z;
        }
        wsum[t] = y;
    }
    __syncthreads();
    int base = (t >= 32) ? wsum[(t >> 5) - 1] : 0;
    int incl = x + base;
    if (i < n) g_rowptr[i] = incl - v;
    if (t == 255) g_bsum[blockIdx.x] = incl;
}

// ---------------- scan pass 2 (fused): each block reduces its bsum prefix ----
__global__ void k_scan3(long long n, int E) {
    __shared__ int red[256];
    int t = threadIdx.x;
    int b = blockIdx.x;
    int s = 0;
    for (int j = t; j < b; j += 256) s += g_bsum[j];
    red[t] = s;
    __syncthreads();
#pragma unroll
    for (int o = 128; o > 0; o >>= 1) {
        if (t < o) red[t] += red[t + o];
        __syncthreads();
    }
    int prefix = red[0];
    long long i = b * 256LL + t;
    if (i < n) {
        int rp = g_rowptr[i] + prefix;
        g_rowptr[i] = rp;
        g_cursor[i] = rp;
        g_dis[i] = rsqrtf((float)(g_deg[i] + 1));
    }
    if (i == 0) g_rowptr[n] = E;
}

// ---------------- scatter src into CSR, 2 edges per thread -------------------
__global__ void k_scatter(const void* ei, long long E) {
    long long e = (blockIdx.x * (long long)blockDim.x + threadIdx.x) * 2;
    if (e >= E) return;
    long long s0, d0, s1 = -1, d1 = -1;
    bool two = (e + 1 < E);
    if (g_is64) {
        const long long* ps = (const long long*)ei + e;
        const long long* pd = (const long long*)ei + E + e;
        s0 = ps[0]; d0 = pd[0];
        if (two) { s1 = ps[1]; d1 = pd[1]; }
    } else {
        const int* ps = (const int*)ei + e;
        const int* pd = (const int*)ei + E + e;
        if (two) {
            int2 sv = *(const int2*)ps;
            int2 dv = *(const int2*)pd;
            s0 = sv.x; d0 = dv.x; s1 = sv.y; d1 = dv.y;
        } else {
            s0 = ps[0]; d0 = pd[0];
        }
    }
    int pos0 = atomicAdd(&g_cursor[d0], 1);
    g_csr[pos0] = (int)s0;
    if (two) {
        int pos1 = atomicAdd(&g_cursor[d1], 1);
        g_csr[pos1] = (int)s1;
    }
}

// ---------------- scale fp16 features by dis[node] ---------------------------
__global__ void k_scale(__half* __restrict__ buf, long long n8) {
    long long idx = blockIdx.x * (long long)blockDim.x + threadIdx.x;
    if (idx >= n8) return;
    long long node = idx >> 3;
    float ds = g_dis[node];
    uint4 u = *(uint4*)(buf + idx * 8);
    __half2* h = (__half2*)&u;
#pragma unroll
    for (int q = 0; q < 4; q++) {
        float2 f = __half22float2(h[q]);
        h[q] = __floats2half2_rn(f.x * ds, f.y * ds);
    }
    *(uint4*)(buf + idx * 8) = u;
}

// ---------------- A-row loaders (16 values) ----------------------------------
__device__ __forceinline__ void loadA16(const float* src, float4* xv) {
#pragma unroll
    for (int q = 0; q < 4; q++) xv[q] = *(const float4*)(src + q * 4);
}
__device__ __forceinline__ void loadA16(const __half* src, float4* xv) {
    uint4 a = *(const uint4*)src;
    uint4 b = *(const uint4*)(src + 8);
    const __half2* ha = (const __half2*)&a;
    const __half2* hb = (const __half2*)&b;
    float2 f0 = __half22float2(ha[0]), f1 = __half22float2(ha[1]);
    float2 f2 = __half22float2(ha[2]), f3 = __half22float2(ha[3]);
    xv[0] = make_float4(f0.x, f0.y, f1.x, f1.y);
    xv[1] = make_float4(f2.x, f2.y, f3.x, f3.y);
    f0 = __half22float2(hb[0]); f1 = __half22float2(hb[1]);
    f2 = __half22float2(hb[2]); f3 = __half22float2(hb[3]);
    xv[2] = make_float4(f0.x, f0.y, f1.x, f1.y);
    xv[3] = make_float4(f2.x, f2.y, f3.x, f3.y);
}

// ---------------- GEMM: C[N,64] = bn?(A)[N,K] @ W[K,64], fp16 out ------------
template <int K, bool BN, bool DIS, typename AT>
__global__ void k_gemm(const AT* __restrict__ A, const float* __restrict__ W,
                       __half* __restrict__ C, long long n,
                       const float* __restrict__ gsum, const float* __restrict__ gsq,
                       const float* __restrict__ gamma, const float* __restrict__ beta,
                       float invN) {
    __shared__ __align__(16) float xsT[32][68];   // [k][row]; 272B row stride
    __shared__ __align__(16) float ws[32][64];    // [k][col]
    __shared__ float bnsc[64], bnsh[64];
    const int tid = threadIdx.x;
    const int tx = tid & 15;
    const int ty = tid >> 4;
    const long long row0 = (long long)blockIdx.x * 64;
    ull acc[8][2] = {};

    if (BN) {
        if (tid < 64) {
            float m   = gsum[tid] * invN;
            float var = gsq[tid] * invN - m * m;
            float s   = rsqrtf(var + EPSV) * gamma[tid];
            bnsc[tid] = s;
            bnsh[tid] = beta[tid] - m * s;
        }
        __syncthreads();
    }

    const int lrow = tid >> 1;
    const int lko  = (tid & 1) * 16;
    const long long grow = row0 + lrow;
    const bool rok = grow < n;

    for (int k0 = 0; k0 < K; k0 += 32) {
        float4 xv[4];
        if (rok) {
            loadA16(A + grow * (long long)K + k0 + lko, xv);
            if (BN) {
#pragma unroll
                for (int q = 0; q < 4; q++) {
                    int c = k0 + lko + q * 4;
                    xv[q].x = xv[q].x * bnsc[c + 0] + bnsh[c + 0];
                    xv[q].y = xv[q].y * bnsc[c + 1] + bnsh[c + 1];
                    xv[q].z = xv[q].z * bnsc[c + 2] + bnsh[c + 2];
                    xv[q].w = xv[q].w * bnsc[c + 3] + bnsh[c + 3];
                }
            }
        } else {
#pragma unroll
            for (int q = 0; q < 4; q++) xv[q] = make_float4(0.f, 0.f, 0.f, 0.f);
        }
        float4 wv[4];
#pragma unroll
        for (int j = 0; j < 4; j++) {
            int fi = tid + j * 128;
            int kk = fi >> 4;
            int cc = (fi & 15) * 4;
            wv[j] = *(const float4*)(W + (long long)(k0 + kk) * 64 + cc);
        }
        __syncthreads();
#pragma unroll
        for (int q = 0; q < 4; q++) {
            xsT[lko + q * 4 + 0][lrow] = xv[q].x;
            xsT[lko + q * 4 + 1][lrow] = xv[q].y;
            xsT[lko + q * 4 + 2][lrow] = xv[q].z;
            xsT[lko + q * 4 + 3][lrow] = xv[q].w;
        }
#pragma unroll
        for (int j = 0; j < 4; j++) {
            int fi = tid + j * 128;
            int kk = fi >> 4;
            int cc = (fi & 15) * 4;
            *(float4*)&ws[kk][cc] = wv[j];
        }
        __syncthreads();
#pragma unroll
        for (int kk = 0; kk < 32; kk++) {
            float4 a0 = *(const float4*)&xsT[kk][ty * 8];
            float4 a1 = *(const float4*)&xsT[kk][ty * 8 + 4];
            const ull* bp = (const ull*)&ws[kk][tx * 4];
            ull b01 = bp[0], b23 = bp[1];
            ull a;
            a = dupf(a0.x); ffma2(acc[0][0], a, b01); ffma2(acc[0][1], a, b23);
            a = dupf(a0.y); ffma2(acc[1][0], a, b01); ffma2(acc[1][1], a, b23);
            a = dupf(a0.z); ffma2(acc[2][0], a, b01); ffma2(acc[2][1], a, b23);
            a = dupf(a0.w); ffma2(acc[3][0], a, b01); ffma2(acc[3][1], a, b23);
            a = dupf(a1.x); ffma2(acc[4][0], a, b01); ffma2(acc[4][1], a, b23);
            a = dupf(a1.y); ffma2(acc[5][0], a, b01); ffma2(acc[5][1], a, b23);
            a = dupf(a1.z); ffma2(acc[6][0], a, b01); ffma2(acc[6][1], a, b23);
            a = dupf(a1.w); ffma2(acc[7][0], a, b01); ffma2(acc[7][1], a, b23);
        }
        __syncthreads();
    }
#pragma unroll
    for (int i = 0; i < 8; i++) {
        long long row = row0 + ty * 8 + i;
        if (row < n) {
            float2 c0 = unpk(acc[i][0]), c1 = unpk(acc[i][1]);
            if (DIS) {
                float ds = g_dis[row];
                c0.x *= ds; c0.y *= ds; c1.x *= ds; c1.y *= ds;
            }
            __half2 h0 = __floats2half2_rn(c0.x, c0.y);
            __half2 h1 = __floats2half2_rn(c1.x, c1.y);
            uint2 u;
            u.x = *(unsigned int*)&h0;
            u.y = *(unsigned int*)&h1;
            *(uint2*)(C + row * 64 + tx * 4) = u;
        }
    }
}

// ---------------- fused CSR gather (dis-prescaled fp16 src) ------------------
// POOL=false: write fp16 activations to out.
// POOL=true : accumulate raw fp32 results into g_pool via per-block staging
//             (batch sorted; 16-node block spans <=16 graphs). No out write.
__device__ __forceinline__ void add4(float4& acc, const uint2& u) {
    float2 a = __half22float2(*(const __half2*)&u.x);
    float2 b = __half22float2(*(const __half2*)&u.y);
    acc.x += a.x; acc.y += a.y;
    acc.z += b.x; acc.w += b.y;
}

template <bool POOL>
__global__ void k_gather(const __half* __restrict__ xwh, const float* __restrict__ bias,
                         __half* __restrict__ out, const void* batch, long long n,
                         float* __restrict__ gsum, float* __restrict__ gsq) {
    __shared__ float ss[HC], sq[HC];
    __shared__ float spool[16][HC];
    __shared__ float scnt[16];
    __shared__ int   sbase;
    int t = threadIdx.x;
    if (t < HC) { ss[t] = 0.f; sq[t] = 0.f; }
    if (POOL) {
        for (int j = t; j < 16 * HC; j += 256) ((float*)spool)[j] = 0.f;
        if (t < 16) scnt[t] = 0.f;
        if (t == 0) {
            long long first = blockIdx.x * 16LL;
            if (first >= n) first = n - 1;
            sbase = (int)ld_idx(batch, first);
        }
    }
    __syncthreads();
    int grp = t >> 4;
    int ch  = (t & 15) * 4;
    long long node = blockIdx.x * 16LL + grp;
    if (node < n) {
        float dd = g_dis[node];
        float4 bv = *(const float4*)(bias + ch);
        uint2 su = *(const uint2*)(xwh + node * 64 + ch);
        float2 s0f = __half22float2(*(__half2*)&su.x);
        float2 s1f = __half22float2(*(__half2*)&su.y);
        float4 nb = make_float4(s0f.x, s0f.y, s1f.x, s1f.y);
        int beg = g_rowptr[node], end = g_rowptr[node + 1];
        int i = beg;
        for (; i + 8 <= end; i += 8) {
            int e0 = g_csr[i],     e1 = g_csr[i + 1], e2 = g_csr[i + 2], e3 = g_csr[i + 3];
            int e4 = g_csr[i + 4], e5 = g_csr[i + 5], e6 = g_csr[i + 6], e7 = g_csr[i + 7];
            uint2 u0 = *(const uint2*)(xwh + (long long)e0 * 64 + ch);
            uint2 u1 = *(const uint2*)(xwh + (long long)e1 * 64 + ch);
            uint2 u2 = *(const uint2*)(xwh + (long long)e2 * 64 + ch);
            uint2 u3 = *(const uint2*)(xwh + (long long)e3 * 64 + ch);
            uint2 u4 = *(const uint2*)(xwh + (long long)e4 * 64 + ch);
            uint2 u5 = *(const uint2*)(xwh + (long long)e5 * 64 + ch);
            uint2 u6 = *(const uint2*)(xwh + (long long)e6 * 64 + ch);
            uint2 u7 = *(const uint2*)(xwh + (long long)e7 * 64 + ch);
            add4(nb, u0); add4(nb, u1); add4(nb, u2); add4(nb, u3);
            add4(nb, u4); add4(nb, u5); add4(nb, u6); add4(nb, u7);
        }
        for (; i < end; i++) {
            int s = g_csr[i];
            uint2 u = *(const uint2*)(xwh + (long long)s * 64 + ch);
            add4(nb, u);
        }
        float4 acc;
        acc.x = fmaxf(fmaf(dd, nb.x, bv.x), 0.f);
        acc.y = fmaxf(fmaf(dd, nb.y, bv.y), 0.f);
        acc.z = fmaxf(fmaf(dd, nb.z, bv.z), 0.f);
        acc.w = fmaxf(fmaf(dd, nb.w, bv.w), 0.f);
        if (!POOL) {
            __half2 h0 = __floats2half2_rn(acc.x, acc.y);
            __half2 h1 = __floats2half2_rn(acc.z, acc.w);
            uint2 o;
            o.x = *(unsigned int*)&h0;
            o.y = *(unsigned int*)&h1;
            *(uint2*)(out + node * 64 + ch) = o;
        } else {
            int slot = (int)ld_idx(batch, node) - sbase;
            atomicAdd(&spool[slot][ch + 0], acc.x);
            atomicAdd(&spool[slot][ch + 1], acc.y);
            atomicAdd(&spool[slot][ch + 2], acc.z);
            atomicAdd(&spool[slot][ch + 3], acc.w);
            if ((t & 15) == 0) atomicAdd(&scnt[slot], 1.f);
        }
        atomicAdd(&ss[ch + 0], acc.x); atomicAdd(&sq[ch + 0], acc.x * acc.x);
        atomicAdd(&ss[ch + 1], acc.y); atomicAdd(&sq[ch + 1], acc.y * acc.y);
        atomicAdd(&ss[ch + 2], acc.z); atomicAdd(&sq[ch + 2], acc.z * acc.z);
        atomicAdd(&ss[ch + 3], acc.w); atomicAdd(&sq[ch + 3], acc.w * acc.w);
    }
    __syncthreads();
    if (t < HC) { atomicAdd(&gsum[t], ss[t]); atomicAdd(&gsq[t], sq[t]); }
    if (POOL) {
#pragma unroll 1
        for (int s = 0; s < 16; s++) {
            if (scnt[s] > 0.f) {
                if (t < HC) atomicAdd(&g_pool[(long long)(sbase + s) * 64 + t], spool[s][t]);
                if (t == HC) atomicAdd(&g_cnt[sbase + s], scnt[s]);
            }
        }
    }
}

// ---------------- fused MLP head: BN2 affine on pooled means + MLP ------------
__global__ void k_mlp(const float* __restrict__ gsum, const float* __restrict__ gsq,
                      const float* __restrict__ gamma, const float* __restrict__ beta,
                      float invN,
                      const float* __restrict__ fw1, const float* __restrict__ fb1,
                      const float* __restrict__ fw2, const float* __restrict__ fb2,
                      const float* __restrict__ fw3, const float* __restrict__ fb3,
                      const float* __restrict__ fw4, const float* __restrict__ fb4,
                      const float* __restrict__ ow,  const float* __restrict__ ob,
                      float* __restrict__ out) {
    __shared__ float p[64], a1[128], a2[64], a3[32], a4[16];
    int g = blockIdx.x, t = threadIdx.x;
    if (t < 64) {
        float m   = gsum[t] * invN;
        float var = gsq[t] * invN - m * m;
        float sc  = rsqrtf(var + EPSV) * gamma[t];
        float sh  = beta[t] - m * sc;
        float cnt = g_cnt[g];
        p[t] = (cnt > 0.f) ? (g_pool[g * 64 + t] / cnt) * sc + sh : 0.f;
    }
    __syncthreads();
    if (t < 128) {
        float a = fb1[t];
#pragma unroll 8
        for (int k = 0; k < 64; k++) a += p[k] * fw1[k * 128 + t];
        a1[t] = fmaxf(a, 0.f);
    }
    __syncthreads();
    if (t < 64) {
        float a = fb2[t];
#pragma unroll 8
        for (int k = 0; k < 128; k++) a += a1[k] * fw2[k * 64 + t];
        a2[t] = fmaxf(a, 0.f);
    }
    __syncthreads();
    if (t < 32) {
        float a = fb3[t];
#pragma unroll 8
        for (int k = 0; k < 64; k++) a += a2[k] * fw3[k * 32 + t];
        a3[t] = fmaxf(a, 0.f);
    }
    __syncthreads();
    if (t < 16) {
        float a = fb4[t];
#pragma unroll
        for (int k = 0; k < 32; k++) a += a3[k] * fw4[k * 16 + t];
        a4[t] = fmaxf(a, 0.f);
    }
    __syncthreads();
    if (t < 2) {
        float a = ob[t];
#pragma unroll
        for (int k = 0; k < 16; k++) a += a4[k] * ow[k * 2 + t];
        out[g * 2 + t] = a;
    }
}

// ---------------- launcher ------------------------------------------------------
extern "C" void kernel_launch(void* const* d_in, const int* in_sizes, int n_in,
                              void* d_out, int out_size) {
    const float* x   = (const float*)d_in[0];
    const void*  ei  = d_in[1];
    const void*  bat = d_in[2];
    const float* w1  = (const float*)d_in[3];
    const float* b1  = (const float*)d_in[4];
    const float* w2  = (const float*)d_in[5];
    const float* b2  = (const float*)d_in[6];
    const float* g1  = (const float*)d_in[7];
    const float* be1 = (const float*)d_in[8];
    const float* g2  = (const float*)d_in[9];
    const float* be2 = (const float*)d_in[10];
    const float* fw1 = (const float*)d_in[11];
    const float* fb1 = (const float*)d_in[12];
    const float* fw2 = (const float*)d_in[13];
    const float* fb2 = (const float*)d_in[14];
    const float* fw3 = (const float*)d_in[15];
    const float* fb3 = (const float*)d_in[16];
    const float* fw4 = (const float*)d_in[17];
    const float* fb4 = (const float*)d_in[18];
    const float* ow  = (const float*)d_in[19];
    const float* ob  = (const float*)d_in[20];
    float* out = (float*)d_out;

    const long long N = in_sizes[0] / 256;   // C = 256
    const long long E = in_sizes[1] / 2;
    const int       G = out_size / 2;
    const float invN = 1.0f / (float)N;

    __half *bufH, *bufF;
    float *sum1, *sq1, *sum2, *sq2;
    cudaGetSymbolAddress((void**)&bufH, g_bufH);
    cudaGetSymbolAddress((void**)&bufF, g_bufF);
    cudaGetSymbolAddress((void**)&sum1, g_sum1);
    cudaGetSymbolAddress((void**)&sq1,  g_sq1);
    cudaGetSymbolAddress((void**)&sum2, g_sum2);
    cudaGetSymbolAddress((void**)&sq2,  g_sq2);

    const int TB = 256;
    const int gN    = (int)((N + TB - 1) / TB);
    const long long E2 = (E + 1) / 2;
    const int gE2   = (int)((E2 + TB - 1) / TB);
    const int gGemm = (int)((N + 63) / 64);
    const int gGath = (int)((N + 15) / 16);
    const int nb    = (int)((N + 255) / 256);
    const long long n8 = N * 8;
    const int gScl  = (int)((n8 + TB - 1) / TB);

    // ---- fork: GEMM1 (independent of CSR/index state) on side stream ----
    cudaEventRecord(hx_fork, 0);
    cudaStreamWaitEvent(hx_s2, hx_fork, 0);
    k_gemm<256, false, false, float><<<gGemm, 128, 0, hx_s2>>>(
        x, w1, bufH, N, nullptr, nullptr, nullptr, nullptr, 0.f);

    // ---- CSR build chain on the main stream ----
    k_zero<<<gN, TB>>>(ei, N);
    k_hist<<<gE2, TB>>>(ei, E);
    k_scan1<<<nb, 256>>>(N);
    k_scan3<<<nb, 256>>>(N, (int)E);
    cudaEventRecord(hx_dis, 0);            // g_dis ready
    k_scatter<<<gE2, TB>>>(ei, E);

    // ---- side stream: scale features once dis is ready (|| scatter) ----
    cudaStreamWaitEvent(hx_s2, hx_dis, 0);
    k_scale<<<gScl, TB, 0, hx_s2>>>(bufH, n8);
    cudaEventRecord(hx_join, hx_s2);

    // ---- join: gather1 needs CSR (main) + scaled features (s2) ----
    cudaStreamWaitEvent(0, hx_join, 0);

    // ---- GCN layer 1 ----
    k_gather<false><<<gGath, 256>>>(bufH, b1, bufF, bat, N, sum1, sq1);

    // ---- GCN layer 2 (BN1 fold + dis-scale in GEMM2 epilogue; pool fused) ----
    k_gemm<64, true, true, __half><<<gGemm, 128>>>(bufF, w2, bufH, N,
                                                   sum1, sq1, g1, be1, invN);
    k_gather<true><<<gGath, 256>>>(bufH, b2, nullptr, bat, N, sum2, sq2);

    // ---- MLP head (applies BN2 affine to pooled raw means) ----
    k_mlp<<<G, 128>>>(sum2, sq2, g2, be2, invN,
                      fw1, fb1, fw2, fb2, fw3, fb3, fw4, fb4, ow, ob, out);
}

// round 17
// speedup vs baseline: 1.0680x; 1.0680x over previous
#include <cuda_runtime.h>
#include <cuda_fp16.h>

typedef unsigned long long ull;

// ---------------- problem constants (shapes fixed by the dataset) -----------
#define MAXN 100000
#define MAXE 3342336
#define HC   64
#define MAXG 512
#define EPSV 1e-5f

// ---------------- device scratch (static; no allocation) --------------------
__device__ __half g_bufH[MAXN * HC];     // scaled projected features, fp16
__device__ __half g_bufF[MAXN * HC];     // hidden activations h, fp16
__device__ float  g_dis[MAXN];           // rsqrt(deg)
__device__ int    g_deg[MAXN];           // in-degree (w/o self loop)
__device__ int    g_rowptr[MAXN + 1];
__device__ int    g_cursor[MAXN];
__device__ int    g_csr[MAXE];           // src ids grouped by dst
__device__ int    g_bsum[512];
__device__ float  g_sum1[HC], g_sq1[HC], g_sum2[HC], g_sq2[HC];
__device__ float  g_pool[MAXG * HC];
__device__ float  g_cnt[MAXG];
__device__ int    g_is64;

// ---------------- host-side stream/event objects (created pre-main) ---------
static cudaStream_t hx_s2;
static cudaEvent_t  hx_fork, hx_dis, hx_join;
namespace {
struct HXInit {
    HXInit() {
        cudaStreamCreateWithFlags(&hx_s2, cudaStreamNonBlocking);
        cudaEventCreateWithFlags(&hx_fork, cudaEventDisableTiming);
        cudaEventCreateWithFlags(&hx_dis,  cudaEventDisableTiming);
        cudaEventCreateWithFlags(&hx_join, cudaEventDisableTiming);
    }
};
static HXInit hx_init;
}

// ---------------- dtype-agnostic index load ---------------------------------
__device__ __forceinline__ long long ld_idx(const void* p, long long i) {
    if (g_is64) return ((const long long*)p)[i];
    return (long long)((const int*)p)[i];
}

// ---------------- packed f32x2 helpers (Blackwell) --------------------------
__device__ __forceinline__ ull dupf(float a) {
    ull r; unsigned int u = __float_as_uint(a);
    asm("mov.b64 %0, {%1, %1};" : "=l"(r) : "r"(u));
    return r;
}
__device__ __forceinline__ void ffma2(ull& d, ull a, ull b) {
    asm("fma.rn.f32x2 %0, %1, %2, %0;" : "+l"(d) : "l"(a), "l"(b));
}
__device__ __forceinline__ float2 unpk(ull v) {
    unsigned int lo, hi;
    asm("mov.b64 {%0, %1}, %2;" : "=r"(lo), "=r"(hi) : "l"(v));
    return make_float2(__uint_as_float(lo), __uint_as_float(hi));
}

// ---------------- init: zero deg/pool/cnt/bn sums (+dtype detect, thread 0) --
__global__ void k_zero(const void* ei, long long n) {
    long long i = blockIdx.x * (long long)blockDim.x + threadIdx.x;
    if (i == 0) {
        const long long* p = (const long long*)ei;
        int ok = 1;
        for (int j = 0; j < 64; j++) {
            long long v = p[j];
            if (v < 0 || v >= n) { ok = 0; break; }
        }
        g_is64 = ok;
    }
    if (i < n)          g_deg[i] = 0;
    if (i < MAXG * HC)  g_pool[i] = 0.0f;
    if (i < MAXG)       g_cnt[i] = 0.0f;
    if (i < HC) { g_sum1[i] = 0.f; g_sq1[i] = 0.f; g_sum2[i] = 0.f; g_sq2[i] = 0.f; }
}

// ---------------- histogram of dst, 2 edges per thread -----------------------
__global__ void k_hist(const void* ei, long long E) {
    long long e = (blockIdx.x * (long long)blockDim.x + threadIdx.x) * 2;
    if (e >= E) return;
    if (g_is64) {
        const long long* p = (const long long*)ei + E + e;
        atomicAdd(&g_deg[p[0]], 1);
        if (e + 1 < E) atomicAdd(&g_deg[p[1]], 1);
    } else {
        const int* p = (const int*)ei + E + e;
        if (e + 1 < E) {
            int2 d = *(const int2*)p;
            atomicAdd(&g_deg[d.x], 1);
            atomicAdd(&g_deg[d.y], 1);
        } else {
            atomicAdd(&g_deg[p[0]], 1);
        }
    }
}

// ---------------- scan pass 1: block-local exclusive scan --------------------
__global__ void k_scan1(long long n) {
    __shared__ int wsum[8];
    int t = threadIdx.x;
    long long i = blockIdx.x * 256LL + t;
    int v = (i < n) ? g_deg[i] : 0;
    int x = v;
#pragma unroll
    for (int o = 1; o < 32; o <<= 1) {
        int y = __shfl_up_sync(~0u, x, o);
        if ((t & 31) >= o) x += y;
    }
    if ((t & 31) == 31) wsum[t >> 5] = x;
    __syncthreads();
    if (t < 8) {
        int y = wsum[t];
#pragma unroll
        for (int o = 1; o < 8; o <<= 1) {
            int z = __shfl_up_sync(0xff, y, o);
            if (t >= o) y += z;
        }
        wsum[t] = y;
    }
    __syncthreads();
    int base = (t >= 32) ? wsum[(t >> 5) - 1] : 0;
    int incl = x + base;
    if (i < n) g_rowptr[i] = incl - v;
    if (t == 255) g_bsum[blockIdx.x] = incl;
}

// ---------------- scan pass 2 (fused): each block reduces its bsum prefix ----
__global__ void k_scan3(long long n, int E) {
    __shared__ int red[256];
    int t = threadIdx.x;
    int b = blockIdx.x;
    int s = 0;
    for (int j = t; j < b; j += 256) s += g_bsum[j];
    red[t] = s;
    __syncthreads();
#pragma unroll
    for (int o = 128; o > 0; o >>= 1) {
        if (t < o) red[t] += red[t + o];
        __syncthreads();
    }
    int prefix = red[0];
    long long i = b * 256LL + t;
    if (i < n) {
        int rp = g_rowptr[i] + prefix;
        g_rowptr[i] = rp;
        g_cursor[i] = rp;
        g_dis[i] = rsqrtf((float)(g_deg[i] + 1));
    }
    if (i == 0) g_rowptr[n] = E;
}

// ---------------- scatter src into CSR, 2 edges per thread -------------------
__global__ void k_scatter(const void* ei, long long E) {
    long long e = (blockIdx.x * (long long)blockDim.x + threadIdx.x) * 2;
    if (e >= E) return;
    long long s0, d0, s1 = -1, d1 = -1;
    bool two = (e + 1 < E);
    if (g_is64) {
        const long long* ps = (const long long*)ei + e;
        const long long* pd = (const long long*)ei + E + e;
        s0 = ps[0]; d0 = pd[0];
        if (two) { s1 = ps[1]; d1 = pd[1]; }
    } else {
        const int* ps = (const int*)ei + e;
        const int* pd = (const int*)ei + E + e;
        if (two) {
            int2 sv = *(const int2*)ps;
            int2 dv = *(const int2*)pd;
            s0 = sv.x; d0 = dv.x; s1 = sv.y; d1 = dv.y;
        } else {
            s0 = ps[0]; d0 = pd[0];
        }
    }
    int pos0 = atomicAdd(&g_cursor[d0], 1);
    g_csr[pos0] = (int)s0;
    if (two) {
        int pos1 = atomicAdd(&g_cursor[d1], 1);
        g_csr[pos1] = (int)s1;
    }
}

// ---------------- scale fp16 features by dis[node] ---------------------------
__global__ void k_scale(__half* __restrict__ buf, long long n8) {
    long long idx = blockIdx.x * (long long)blockDim.x + threadIdx.x;
    if (idx >= n8) return;
    long long node = idx >> 3;
    float ds = g_dis[node];
    uint4 u = *(uint4*)(buf + idx * 8);
    __half2* h = (__half2*)&u;
#pragma unroll
    for (int q = 0; q < 4; q++) {
        float2 f = __half22float2(h[q]);
        h[q] = __floats2half2_rn(f.x * ds, f.y * ds);
    }
    *(uint4*)(buf + idx * 8) = u;
}

// ---------------- A-row loaders (16 values) ----------------------------------
__device__ __forceinline__ void loadA16(const float* src, float4* xv) {
#pragma unroll
    for (int q = 0; q < 4; q++) xv[q] = *(const float4*)(src + q * 4);
}
__device__ __forceinline__ void loadA16(const __half* src, float4* xv) {
    uint4 a = *(const uint4*)src;
    uint4 b = *(const uint4*)(src + 8);
    const __half2* ha = (const __half2*)&a;
    const __half2* hb = (const __half2*)&b;
    float2 f0 = __half22float2(ha[0]), f1 = __half22float2(ha[1]);
    float2 f2 = __half22float2(ha[2]), f3 = __half22float2(ha[3]);
    xv[0] = make_float4(f0.x, f0.y, f1.x, f1.y);
    xv[1] = make_float4(f2.x, f2.y, f3.x, f3.y);
    f0 = __half22float2(hb[0]); f1 = __half22float2(hb[1]);
    f2 = __half22float2(hb[2]); f3 = __half22float2(hb[3]);
    xv[2] = make_float4(f0.x, f0.y, f1.x, f1.y);
    xv[3] = make_float4(f2.x, f2.y, f3.x, f3.y);
}

// ---------------- GEMM: C[N,64] = bn?(A)[N,K] @ W[K,64], fp16 out ------------
template <int K, bool BN, bool DIS, typename AT>
__global__ void k_gemm(const AT* __restrict__ A, const float* __restrict__ W,
                       __half* __restrict__ C, long long n,
                       const float* __restrict__ gsum, const float* __restrict__ gsq,
                       const float* __restrict__ gamma, const float* __restrict__ beta,
                       float invN) {
    __shared__ __align__(16) float xsT[32][68];   // [k][row]; 272B row stride
    __shared__ __align__(16) float ws[32][64];    // [k][col]
    __shared__ float bnsc[64], bnsh[64];
    const int tid = threadIdx.x;
    const int tx = tid & 15;
    const int ty = tid >> 4;
    const long long row0 = (long long)blockIdx.x * 64;
    ull acc[8][2] = {};

    if (BN) {
        if (tid < 64) {
            float m   = gsum[tid] * invN;
            float var = gsq[tid] * invN - m * m;
            float s   = rsqrtf(var + EPSV) * gamma[tid];
            bnsc[tid] = s;
            bnsh[tid] = beta[tid] - m * s;
        }
        __syncthreads();
    }

    const int lrow = tid >> 1;
    const int lko  = (tid & 1) * 16;
    const long long grow = row0 + lrow;
    const bool rok = grow < n;

    for (int k0 = 0; k0 < K; k0 += 32) {
        float4 xv[4];
        if (rok) {
            loadA16(A + grow * (long long)K + k0 + lko, xv);
            if (BN) {
#pragma unroll
                for (int q = 0; q < 4; q++) {
                    int c = k0 + lko + q * 4;
                    xv[q].x = xv[q].x * bnsc[c + 0] + bnsh[c + 0];
                    xv[q].y = xv[q].y * bnsc[c + 1] + bnsh[c + 1];
                    xv[q].z = xv[q].z * bnsc[c + 2] + bnsh[c + 2];
                    xv[q].w = xv[q].w * bnsc[c + 3] + bnsh[c + 3];
                }
            }
        } else {
#pragma unroll
            for (int q = 0; q < 4; q++) xv[q] = make_float4(0.f, 0.f, 0.f, 0.f);
        }
        float4 wv[4];
#pragma unroll
        for (int j = 0; j < 4; j++) {
            int fi = tid + j * 128;
            int kk = fi >> 4;
            int cc = (fi & 15) * 4;
            wv[j] = *(const float4*)(W + (long long)(k0 + kk) * 64 + cc);
        }
        __syncthreads();
#pragma unroll
        for (int q = 0; q < 4; q++) {
            xsT[lko + q * 4 + 0][lrow] = xv[q].x;
            xsT[lko + q * 4 + 1][lrow] = xv[q].y;
            xsT[lko + q * 4 + 2][lrow] = xv[q].z;
            xsT[lko + q * 4 + 3][lrow] = xv[q].w;
        }
#pragma unroll
        for (int j = 0; j < 4; j++) {
            int fi = tid + j * 128;
            int kk = fi >> 4;
            int cc = (fi & 15) * 4;
            *(float4*)&ws[kk][cc] = wv[j];
        }
        __syncthreads();
#pragma unroll
        for (int kk = 0; kk < 32; kk++) {
            float4 a0 = *(const float4*)&xsT[kk][ty * 8];
            float4 a1 = *(const float4*)&xsT[kk][ty * 8 + 4];
            const ull* bp = (const ull*)&ws[kk][tx * 4];
            ull b01 = bp[0], b23 = bp[1];
            ull a;
            a = dupf(a0.x); ffma2(acc[0][0], a, b01); ffma2(acc[0][1], a, b23);
            a = dupf(a0.y); ffma2(acc[1][0], a, b01); ffma2(acc[1][1], a, b23);
            a = dupf(a0.z); ffma2(acc[2][0], a, b01); ffma2(acc[2][1], a, b23);
            a = dupf(a0.w); ffma2(acc[3][0], a, b01); ffma2(acc[3][1], a, b23);
            a = dupf(a1.x); ffma2(acc[4][0], a, b01); ffma2(acc[4][1], a, b23);
            a = dupf(a1.y); ffma2(acc[5][0], a, b01); ffma2(acc[5][1], a, b23);
            a = dupf(a1.z); ffma2(acc[6][0], a, b01); ffma2(acc[6][1], a, b23);
            a = dupf(a1.w); ffma2(acc[7][0], a, b01); ffma2(acc[7][1], a, b23);
        }
        __syncthreads();
    }
#pragma unroll
    for (int i = 0; i < 8; i++) {
        long long row = row0 + ty * 8 + i;
        if (row < n) {
            float2 c0 = unpk(acc[i][0]), c1 = unpk(acc[i][1]);
            if (DIS) {
                float ds = g_dis[row];
                c0.x *= ds; c0.y *= ds; c1.x *= ds; c1.y *= ds;
            }
            __half2 h0 = __floats2half2_rn(c0.x, c0.y);
            __half2 h1 = __floats2half2_rn(c1.x, c1.y);
            uint2 u;
            u.x = *(unsigned int*)&h0;
            u.y = *(unsigned int*)&h1;
            *(uint2*)(C + row * 64 + tx * 4) = u;
        }
    }
}

// ---------------- fused CSR gather (dis-prescaled fp16 src, fp16 out) --------
// Stats epilogue: lanes l and l+16 share the same channel group -> pair-reduce
// via shfl before the shared atomic (halves shared-atomic traffic).
__device__ __forceinline__ void add4(float4& acc, const uint2& u) {
    float2 a = __half22float2(*(const __half2*)&u.x);
    float2 b = __half22float2(*(const __half2*)&u.y);
    acc.x += a.x; acc.y += a.y;
    acc.z += b.x; acc.w += b.y;
}

__global__ void k_gather(const __half* __restrict__ xwh, const float* __restrict__ bias,
                         __half* __restrict__ out, long long n,
                         float* __restrict__ gsum, float* __restrict__ gsq) {
    __shared__ float ss[HC], sq[HC];
    int t = threadIdx.x;
    if (t < HC) { ss[t] = 0.f; sq[t] = 0.f; }
    __syncthreads();
    int grp = t >> 4;
    int ch  = (t & 15) * 4;
    long long node = blockIdx.x * 16LL + grp;
    float4 acc = make_float4(0.f, 0.f, 0.f, 0.f);
    if (node < n) {
        float dd = g_dis[node];
        float4 bv = *(const float4*)(bias + ch);
        uint2 su = *(const uint2*)(xwh + node * 64 + ch);
        float2 s0f = __half22float2(*(__half2*)&su.x);
        float2 s1f = __half22float2(*(__half2*)&su.y);
        float4 nb = make_float4(s0f.x, s0f.y, s1f.x, s1f.y);
        int beg = g_rowptr[node], end = g_rowptr[node + 1];
        int i = beg;
        for (; i + 8 <= end; i += 8) {
            int e0 = g_csr[i],     e1 = g_csr[i + 1], e2 = g_csr[i + 2], e3 = g_csr[i + 3];
            int e4 = g_csr[i + 4], e5 = g_csr[i + 5], e6 = g_csr[i + 6], e7 = g_csr[i + 7];
            uint2 u0 = *(const uint2*)(xwh + (long long)e0 * 64 + ch);
            uint2 u1 = *(const uint2*)(xwh + (long long)e1 * 64 + ch);
            uint2 u2 = *(const uint2*)(xwh + (long long)e2 * 64 + ch);
            uint2 u3 = *(const uint2*)(xwh + (long long)e3 * 64 + ch);
            uint2 u4 = *(const uint2*)(xwh + (long long)e4 * 64 + ch);
            uint2 u5 = *(const uint2*)(xwh + (long long)e5 * 64 + ch);
            uint2 u6 = *(const uint2*)(xwh + (long long)e6 * 64 + ch);
            uint2 u7 = *(const uint2*)(xwh + (long long)e7 * 64 + ch);
            add4(nb, u0); add4(nb, u1); add4(nb, u2); add4(nb, u3);
            add4(nb, u4); add4(nb, u5); add4(nb, u6); add4(nb, u7);
        }
        for (; i < end; i++) {
            int s = g_csr[i];
            uint2 u = *(const uint2*)(xwh + (long long)s * 64 + ch);
            add4(nb, u);
        }
        acc.x = fmaxf(fmaf(dd, nb.x, bv.x), 0.f);
        acc.y = fmaxf(fmaf(dd, nb.y, bv.y), 0.f);
        acc.z = fmaxf(fmaf(dd, nb.z, bv.z), 0.f);
        acc.w = fmaxf(fmaf(dd, nb.w, bv.w), 0.f);
        __half2 h0 = __floats2half2_rn(acc.x, acc.y);
        __half2 h1 = __floats2half2_rn(acc.z, acc.w);
        uint2 o;
        o.x = *(unsigned int*)&h0;
        o.y = *(unsigned int*)&h1;
        *(uint2*)(out + node * 64 + ch) = o;
    }
    // pair-reduce (lane, lane+16) then one atomic per channel per warp
    float qx = acc.x * acc.x, qy = acc.y * acc.y;
    float qz = acc.z * acc.z, qw = acc.w * acc.w;
    acc.x += __shfl_down_sync(~0u, acc.x, 16);
    acc.y += __shfl_down_sync(~0u, acc.y, 16);
    acc.z += __shfl_down_sync(~0u, acc.z, 16);
    acc.w += __shfl_down_sync(~0u, acc.w, 16);
    qx += __shfl_down_sync(~0u, qx, 16);
    qy += __shfl_down_sync(~0u, qy, 16);
    qz += __shfl_down_sync(~0u, qz, 16);
    qw += __shfl_down_sync(~0u, qw, 16);
    if ((t & 31) < 16) {
        atomicAdd(&ss[ch + 0], acc.x); atomicAdd(&sq[ch + 0], qx);
        atomicAdd(&ss[ch + 1], acc.y); atomicAdd(&sq[ch + 1], qy);
        atomicAdd(&ss[ch + 2], acc.z); atomicAdd(&sq[ch + 2], qz);
        atomicAdd(&ss[ch + 3], acc.w); atomicAdd(&sq[ch + 3], qw);
    }
    __syncthreads();
    if (t < HC) { atomicAdd(&gsum[t], ss[t]); atomicAdd(&gsq[t], sq[t]); }
}

// ---------------- BN apply + mean pool (fp16 input): 8 nodes/thread ----------
__global__ void k_bnpool(const __half* __restrict__ buf, const float* __restrict__ gsum,
                         const float* __restrict__ gsq, const float* __restrict__ gamma,
                         const float* __restrict__ beta, const void* batch,
                         float invN, long long n) {
    long long tid = blockIdx.x * (long long)blockDim.x + threadIdx.x;
    long long grpi = tid >> 6;
    int c = (int)(tid & 63);
    long long i0 = grpi * 8;
    if (i0 >= n) return;
    float m   = gsum[c] * invN;
    float var = gsq[c] * invN - m * m;
    float sc  = rsqrtf(var + EPSV) * gamma[c];
    float sh  = beta[c] - m * sc;
    long long curb = ld_idx(batch, i0);
    float accv = 0.f;
    float accc = 0.f;
#pragma unroll
    for (int j = 0; j < 8; j++) {
        long long node = i0 + j;
        if (node >= n) break;
        long long b = ld_idx(batch, node);
        if (b != curb) {
            atomicAdd(&g_pool[curb * 64 + c], accv);
            if (c == 0) atomicAdd(&g_cnt[curb], accc);
            accv = 0.f; accc = 0.f; curb = b;
        }
        accv += __half2float(buf[node * 64 + c]) * sc + sh;
        accc += 1.f;
    }
    atomicAdd(&g_pool[curb * 64 + c], accv);
    if (c == 0) atomicAdd(&g_cnt[curb], accc);
}

// ---------------- fused MLP head: one block per graph ------------------------
__global__ void k_mlp(const float* __restrict__ fw1, const float* __restrict__ fb1,
                      const float* __restrict__ fw2, const float* __restrict__ fb2,
                      const float* __restrict__ fw3, const float* __restrict__ fb3,
                      const float* __restrict__ fw4, const float* __restrict__ fb4,
                      const float* __restrict__ ow,  const float* __restrict__ ob,
                      float* __restrict__ out) {
    __shared__ float p[64], a1[128], a2[64], a3[32], a4[16];
    int g = blockIdx.x, t = threadIdx.x;
    float inv = 1.0f / fmaxf(g_cnt[g], 1.0f);
    if (t < 64) p[t] = g_pool[g * 64 + t] * inv;
    __syncthreads();
    if (t < 128) {
        float a = fb1[t];
#pragma unroll 8
        for (int k = 0; k < 64; k++) a += p[k] * fw1[k * 128 + t];
        a1[t] = fmaxf(a, 0.f);
    }
    __syncthreads();
    if (t < 64) {
        float a = fb2[t];
#pragma unroll 8
        for (int k = 0; k < 128; k++) a += a1[k] * fw2[k * 64 + t];
        a2[t] = fmaxf(a, 0.f);
    }
    __syncthreads();
    if (t < 32) {
        float a = fb3[t];
#pragma unroll 8
        for (int k = 0; k < 64; k++) a += a2[k] * fw3[k * 32 + t];
        a3[t] = fmaxf(a, 0.f);
    }
    __syncthreads();
    if (t < 16) {
        float a = fb4[t];
#pragma unroll
        for (int k = 0; k < 32; k++) a += a3[k] * fw4[k * 16 + t];
        a4[t] = fmaxf(a, 0.f);
    }
    __syncthreads();
    if (t < 2) {
        float a = ob[t];
#pragma unroll
        for (int k = 0; k < 16; k++) a += a4[k] * ow[k * 2 + t];
        out[g * 2 + t] = a;
    }
}

// ---------------- launcher ------------------------------------------------------
extern "C" void kernel_launch(void* const* d_in, const int* in_sizes, int n_in,
                              void* d_out, int out_size) {
    const float* x   = (const float*)d_in[0];
    const void*  ei  = d_in[1];
    const void*  bat = d_in[2];
    const float* w1  = (const float*)d_in[3];
    const float* b1  = (const float*)d_in[4];
    const float* w2  = (const float*)d_in[5];
    const float* b2  = (const float*)d_in[6];
    const float* g1  = (const float*)d_in[7];
    const float* be1 = (const float*)d_in[8];
    const float* g2  = (const float*)d_in[9];
    const float* be2 = (const float*)d_in[10];
    const float* fw1 = (const float*)d_in[11];
    const float* fb1 = (const float*)d_in[12];
    const float* fw2 = (const float*)d_in[13];
    const float* fb2 = (const float*)d_in[14];
    const float* fw3 = (const float*)d_in[15];
    const float* fb3 = (const float*)d_in[16];
    const float* fw4 = (const float*)d_in[17];
    const float* fb4 = (const float*)d_in[18];
    const float* ow  = (const float*)d_in[19];
    const float* ob  = (const float*)d_in[20];
    float* out = (float*)d_out;

    const long long N = in_sizes[0] / 256;   // C = 256
    const long long E = in_sizes[1] / 2;
    const int       G = out_size / 2;
    const float invN = 1.0f / (float)N;

    __half *bufH, *bufF;
    float *sum1, *sq1, *sum2, *sq2;
    cudaGetSymbolAddress((void**)&bufH, g_bufH);
    cudaGetSymbolAddress((void**)&bufF, g_bufF);
    cudaGetSymbolAddress((void**)&sum1, g_sum1);
    cudaGetSymbolAddress((void**)&sq1,  g_sq1);
    cudaGetSymbolAddress((void**)&sum2, g_sum2);
    cudaGetSymbolAddress((void**)&sq2,  g_sq2);

    const int TB = 256;
    const int gN    = (int)((N + TB - 1) / TB);
    const long long E2 = (E + 1) / 2;
    const int gE2   = (int)((E2 + TB - 1) / TB);
    const int gGemm = (int)((N + 63) / 64);
    const int gGath = (int)((N + 15) / 16);
    const int nb    = (int)((N + 255) / 256);
    const long long n8 = N * 8;
    const int gScl  = (int)((n8 + TB - 1) / TB);
    const long long ngrp8 = (N + 7) / 8;
    const int gBnp  = (int)((ngrp8 * 64 + TB - 1) / TB);

    // ---- fork: GEMM1 (independent of CSR/index state) on side stream ----
    cudaEventRecord(hx_fork, 0);
    cudaStreamWaitEvent(hx_s2, hx_fork, 0);
    k_gemm<256, false, false, float><<<gGemm, 128, 0, hx_s2>>>(
        x, w1, bufH, N, nullptr, nullptr, nullptr, nullptr, 0.f);

    // ---- CSR build chain on the main stream ----
    k_zero<<<gN, TB>>>(ei, N);
    k_hist<<<gE2, TB>>>(ei, E);
    k_scan1<<<nb, 256>>>(N);
    k_scan3<<<nb, 256>>>(N, (int)E);
    cudaEventRecord(hx_dis, 0);            // g_dis ready
    k_scatter<<<gE2, TB>>>(ei, E);

    // ---- side stream: scale features once dis is ready (|| scatter) ----
    cudaStreamWaitEvent(hx_s2, hx_dis, 0);
    k_scale<<<gScl, TB, 0, hx_s2>>>(bufH, n8);
    cudaEventRecord(hx_join, hx_s2);

    // ---- join: gather1 needs CSR (main) + scaled features (s2) ----
    cudaStreamWaitEvent(0, hx_join, 0);

    // ---- GCN layer 1 ----
    k_gather<<<gGath, 256>>>(bufH, b1, bufF, N, sum1, sq1);

    // ---- GCN layer 2 (BN1 fold + dis-scale in GEMM2 epilogue) ----
    k_gemm<64, true, true, __half><<<gGemm, 128>>>(bufF, w2, bufH, N,
                                                   sum1, sq1, g1, be1, invN);
    k_gather<<<gGath, 256>>>(bufH, b2, bufF, N, sum2, sq2);
    k_bnpool<<<gBnp, TB>>>(bufF, sum2, sq2, g2, be2, bat, invN, N);

    // ---- MLP head ----
    k_mlp<<<G, 128>>>(fw1, fb1, fw2, fb2, fw3, fb3, fw4, fb4, ow, ob, out);
}